// round 2
// baseline (speedup 1.0000x reference)
#include <cuda_runtime.h>
#include <cuda_bf16.h>
#include <cstdint>

// ---------------------------------------------------------------------------
// Encoder: out = Attn(x) for x [8, 2048, 1024], single head, dk = 1024.
//   Q = x wqT, K = x wkT, V = x wvT          (NT gemms)
//   S = Q KT / 32 (per batch)                (NT gemm, batched)
//   P = softmax(S, axis=-1)
//   ctx = P V (per batch)                    (NN gemm, batched)
//   out = ctx woT                            (NT gemm)
// Round 1: fp32 tiled SGEMM baseline with register-prefetch double buffering.
// ---------------------------------------------------------------------------

#define BATCH   8
#define SEQ     2048
#define DMODEL  1024
#define MTOT    (BATCH * SEQ)          // 16384

// Static device scratch (allocation-free rule: __device__ globals are allowed)
__device__ float g_Q[MTOT * DMODEL];
__device__ float g_K[MTOT * DMODEL];
__device__ float g_V[MTOT * DMODEL];
__device__ float g_S[BATCH * SEQ * SEQ];
__device__ float g_CTX[MTOT * DMODEL];

// ---------------------------------------------------------------------------
// Tiled SGEMM: C[M,N] = alpha * A[M,K] * op(B)
//   BT = true : B is [N,K] row-major (C = A * B^T)   -- both operands K-contig
//   BT = false: B is [K,N] row-major (C = A * B)
// BM=BN=128, BK=16, 256 threads, 8x8 microtile per thread.
// Register-prefetch double buffering: next k-tile's global loads issue before
// the current tile's compute, landing in registers; stored to smem after the
// compute-side __syncthreads.
// All dims used here are multiples of 128 -> no bounds checks.
// ---------------------------------------------------------------------------
#define BM 128
#define BN 128
#define BK 16
#define TM 8
#define TN 8

template <bool BT>
__global__ __launch_bounds__(256, 2)
void gemm_kernel(const float* __restrict__ A, const float* __restrict__ B,
                 float* __restrict__ C, int M, int N, int K, float alpha,
                 size_t strideA, size_t strideB, size_t strideC)
{
    __shared__ float As[BK][BM];
    __shared__ float Bs[BK][BN];

    const int bz = blockIdx.z;
    A += (size_t)bz * strideA;
    B += (size_t)bz * strideB;
    C += (size_t)bz * strideC;

    const int row0 = blockIdx.y * BM;
    const int col0 = blockIdx.x * BN;
    const int tid  = threadIdx.x;
    const int tx   = tid & 15;          // 0..15  -> N direction
    const int ty   = tid >> 4;          // 0..15  -> M direction

    // loader mapping for K-contiguous tiles (A always; B when BT)
    const int lr = tid >> 2;            // 0..63 (row within tile, +64 second pass)
    const int lc = (tid & 3) * 4;       // 0,4,8,12 (k offset)
    // loader mapping for N-contiguous B tiles (when !BT)
    const int br = tid >> 5;            // 0..7 (k row, +8 second pass)
    const int bc = (tid & 31) * 4;      // 0..124 (n offset)

    float acc[TM][TN];
#pragma unroll
    for (int i = 0; i < TM; i++)
#pragma unroll
        for (int j = 0; j < TN; j++) acc[i][j] = 0.f;

    float4 pa[2], pb[2];

    // ---- load helpers (as lambdas so prefetch + prologue share code) ----
    auto load_tiles = [&](int k0) {
#pragma unroll
        for (int r = 0; r < 2; r++)
            pa[r] = *reinterpret_cast<const float4*>(
                A + (size_t)(row0 + lr + r * 64) * K + k0 + lc);
        if (BT) {
#pragma unroll
            for (int r = 0; r < 2; r++)
                pb[r] = *reinterpret_cast<const float4*>(
                    B + (size_t)(col0 + lr + r * 64) * K + k0 + lc);
        } else {
#pragma unroll
            for (int r = 0; r < 2; r++)
                pb[r] = *reinterpret_cast<const float4*>(
                    B + (size_t)(k0 + br + r * 8) * N + col0 + bc);
        }
    };
    auto store_tiles = [&]() {
#pragma unroll
        for (int r = 0; r < 2; r++) {
            const int m = lr + r * 64;
            As[lc + 0][m] = pa[r].x;
            As[lc + 1][m] = pa[r].y;
            As[lc + 2][m] = pa[r].z;
            As[lc + 3][m] = pa[r].w;
        }
        if (BT) {
#pragma unroll
            for (int r = 0; r < 2; r++) {
                const int n = lr + r * 64;
                Bs[lc + 0][n] = pb[r].x;
                Bs[lc + 1][n] = pb[r].y;
                Bs[lc + 2][n] = pb[r].z;
                Bs[lc + 3][n] = pb[r].w;
            }
        } else {
#pragma unroll
            for (int r = 0; r < 2; r++)
                *reinterpret_cast<float4*>(&Bs[br + r * 8][bc]) = pb[r];
        }
    };

    // prologue: first tile
    load_tiles(0);
    store_tiles();
    __syncthreads();

    for (int k0 = 0; k0 < K; k0 += BK) {
        const bool has_next = (k0 + BK < K);
        if (has_next) load_tiles(k0 + BK);    // prefetch into registers

        // ---- compute current tile ----
#pragma unroll
        for (int kk = 0; kk < BK; kk++) {
            float a[TM], b[TN];
#pragma unroll
            for (int i = 0; i < TM; i++) a[i] = As[kk][ty * TM + i];
#pragma unroll
            for (int j = 0; j < TN; j++) b[j] = Bs[kk][tx * TN + j];
#pragma unroll
            for (int i = 0; i < TM; i++)
#pragma unroll
                for (int j = 0; j < TN; j++)
                    acc[i][j] += a[i] * b[j];
        }
        __syncthreads();
        if (has_next) {
            store_tiles();
            __syncthreads();
        }
    }

    // ---- epilogue ----
#pragma unroll
    for (int i = 0; i < TM; i++) {
        const size_t m = row0 + ty * TM + i;
#pragma unroll
        for (int j = 0; j < TN; j += 4) {
            float4 v;
            v.x = acc[i][j + 0] * alpha;
            v.y = acc[i][j + 1] * alpha;
            v.z = acc[i][j + 2] * alpha;
            v.w = acc[i][j + 3] * alpha;
            *reinterpret_cast<float4*>(C + m * N + col0 + tx * TN + j) = v;
        }
    }
}

// ---------------------------------------------------------------------------
// Row softmax over 2048 columns. One block (256 threads) per row, 8 f32/thread.
// ---------------------------------------------------------------------------
__global__ __launch_bounds__(256)
void softmax_kernel(float* __restrict__ S)
{
    float* row = S + (size_t)blockIdx.x * SEQ;
    const int tid = threadIdx.x;

    float4 v0 = reinterpret_cast<float4*>(row)[tid];
    float4 v1 = reinterpret_cast<float4*>(row)[tid + 256];

    float m = fmaxf(fmaxf(fmaxf(v0.x, v0.y), fmaxf(v0.z, v0.w)),
                    fmaxf(fmaxf(v1.x, v1.y), fmaxf(v1.z, v1.w)));

    __shared__ float red[8];
#pragma unroll
    for (int o = 16; o > 0; o >>= 1)
        m = fmaxf(m, __shfl_xor_sync(0xffffffffu, m, o));
    if ((tid & 31) == 0) red[tid >> 5] = m;
    __syncthreads();
    m = red[0];
#pragma unroll
    for (int w = 1; w < 8; w++) m = fmaxf(m, red[w]);
    __syncthreads();   // red reused below

    v0.x = __expf(v0.x - m); v0.y = __expf(v0.y - m);
    v0.z = __expf(v0.z - m); v0.w = __expf(v0.w - m);
    v1.x = __expf(v1.x - m); v1.y = __expf(v1.y - m);
    v1.z = __expf(v1.z - m); v1.w = __expf(v1.w - m);

    float s = (v0.x + v0.y + v0.z + v0.w) + (v1.x + v1.y + v1.z + v1.w);
#pragma unroll
    for (int o = 16; o > 0; o >>= 1)
        s += __shfl_xor_sync(0xffffffffu, s, o);
    if ((tid & 31) == 0) red[tid >> 5] = s;
    __syncthreads();
    s = red[0];
#pragma unroll
    for (int w = 1; w < 8; w++) s += red[w];

    const float inv = 1.0f / s;
    v0.x *= inv; v0.y *= inv; v0.z *= inv; v0.w *= inv;
    v1.x *= inv; v1.y *= inv; v1.z *= inv; v1.w *= inv;

    reinterpret_cast<float4*>(row)[tid]       = v0;
    reinterpret_cast<float4*>(row)[tid + 256] = v1;
}

// ---------------------------------------------------------------------------
// Launch
// ---------------------------------------------------------------------------
extern "C" void kernel_launch(void* const* d_in, const int* in_sizes, int n_in,
                              void* d_out, int out_size)
{
    const float* x  = (const float*)d_in[0];
    const float* wq = (const float*)d_in[1];
    const float* wk = (const float*)d_in[2];
    const float* wv = (const float*)d_in[3];
    const float* wo = (const float*)d_in[4];
    float* out = (float*)d_out;

    float *pQ, *pK, *pV, *pS, *pC;
    cudaGetSymbolAddress((void**)&pQ, g_Q);
    cudaGetSymbolAddress((void**)&pK, g_K);
    cudaGetSymbolAddress((void**)&pV, g_V);
    cudaGetSymbolAddress((void**)&pS, g_S);
    cudaGetSymbolAddress((void**)&pC, g_CTX);

    const dim3 blk(256);

    // Q/K/V projections: [16384,1024] = x[16384,1024] * W^T, NT
    {
        dim3 grid(DMODEL / BN, MTOT / BM, 1);
        gemm_kernel<true><<<grid, blk>>>(x, wq, pQ, MTOT, DMODEL, DMODEL, 1.0f, 0, 0, 0);
        gemm_kernel<true><<<grid, blk>>>(x, wk, pK, MTOT, DMODEL, DMODEL, 1.0f, 0, 0, 0);
        gemm_kernel<true><<<grid, blk>>>(x, wv, pV, MTOT, DMODEL, DMODEL, 1.0f, 0, 0, 0);
    }

    // Scores: per batch, S = (Q K^T) / sqrt(1024), NT batched
    {
        dim3 grid(SEQ / BN, SEQ / BM, BATCH);
        gemm_kernel<true><<<grid, blk>>>(pQ, pK, pS, SEQ, SEQ, DMODEL, 0.03125f,
                                         (size_t)SEQ * DMODEL,
                                         (size_t)SEQ * DMODEL,
                                         (size_t)SEQ * SEQ);
    }

    // Softmax over rows
    softmax_kernel<<<BATCH * SEQ, blk>>>(pS);

    // ctx = P V, NN batched
    {
        dim3 grid(DMODEL / BN, SEQ / BM, BATCH);
        gemm_kernel<false><<<grid, blk>>>(pS, pV, pC, SEQ, DMODEL, SEQ, 1.0f,
                                          (size_t)SEQ * SEQ,
                                          (size_t)SEQ * DMODEL,
                                          (size_t)SEQ * DMODEL);
    }

    // out = ctx wo^T, NT
    {
        dim3 grid(DMODEL / BN, MTOT / BM, 1);
        gemm_kernel<true><<<grid, blk>>>(pC, wo, out, MTOT, DMODEL, DMODEL, 1.0f, 0, 0, 0);
    }
}

// round 5
// speedup vs baseline: 2.6346x; 2.6346x over previous
#include <cuda_runtime.h>
#include <cuda_bf16.h>
#include <cstdint>

// ===========================================================================
// Encoder (single-head attention, d=1024, batch 8, seq 2048).
// Target compiles as plain sm_100 (no 'a'), so tcgen05/TMEM are unavailable.
// Tensor path: ldmatrix + mma.sync.m16n8k16 bf16 (HMMA), with bf16x3 hi/lo
// split for fp32-grade accuracy:  A*B ~= Ahi*Bhi + Alo*Bhi + Ahi*Blo.
// All operands are pre-split bf16 hi/lo arrays; GEMM epilogues emit the next
// stage's hi/lo directly. All GEMMs are NT (K-contiguous both sides).
// ===========================================================================

#define BATCH   8
#define SEQ     2048
#define DMODEL  1024
#define MTOT    (BATCH * SEQ)

typedef __nv_bfloat16 bf16;

// ---- static device scratch ------------------------------------------------
__device__ bf16 g_xhi [MTOT * DMODEL];
__device__ bf16 g_xlo [MTOT * DMODEL];
__device__ bf16 g_whi [4][DMODEL * DMODEL];   // q,k,v,o
__device__ bf16 g_wlo [4][DMODEL * DMODEL];
__device__ bf16 g_Qhi [MTOT * DMODEL];
__device__ bf16 g_Qlo [MTOT * DMODEL];
__device__ bf16 g_Khi [MTOT * DMODEL];
__device__ bf16 g_Klo [MTOT * DMODEL];
__device__ bf16 g_Vhi [MTOT * DMODEL];
__device__ bf16 g_Vlo [MTOT * DMODEL];
__device__ bf16 g_Vthi[MTOT * DMODEL];
__device__ bf16 g_Vtlo[MTOT * DMODEL];
__device__ float g_S  [(size_t)BATCH * SEQ * SEQ];
__device__ bf16 g_Phi [(size_t)BATCH * SEQ * SEQ];
__device__ bf16 g_Plo [(size_t)BATCH * SEQ * SEQ];
__device__ bf16 g_Chi [MTOT * DMODEL];
__device__ bf16 g_Clo [MTOT * DMODEL];

// ---- PTX helpers ----------------------------------------------------------
__device__ __forceinline__ uint32_t smem_u32(const void* p) {
    uint32_t a;
    asm("{ .reg .u64 t; cvta.to.shared.u64 t, %1; cvt.u32.u64 %0, t; }"
        : "=r"(a) : "l"(p));
    return a;
}

__device__ __forceinline__ void cp_async16(uint32_t dst, const void* src) {
    asm volatile("cp.async.cg.shared.global [%0], [%1], 16;"
                 :: "r"(dst), "l"(src) : "memory");
}
#define CP_COMMIT() asm volatile("cp.async.commit_group;" ::: "memory")
#define CP_WAIT1()  asm volatile("cp.async.wait_group 1;"  ::: "memory")
#define CP_WAIT0()  asm volatile("cp.async.wait_group 0;"  ::: "memory")

__device__ __forceinline__ void ldm_x4(uint32_t* r, uint32_t addr) {
    asm volatile("ldmatrix.sync.aligned.m8n8.x4.shared.b16 {%0,%1,%2,%3}, [%4];"
                 : "=r"(r[0]), "=r"(r[1]), "=r"(r[2]), "=r"(r[3]) : "r"(addr));
}

__device__ __forceinline__ void mma16816(float* d, const uint32_t* a,
                                         uint32_t b0, uint32_t b1) {
    asm volatile("mma.sync.aligned.m16n8k16.row.col.f32.bf16.bf16.f32 "
                 "{%0,%1,%2,%3}, {%4,%5,%6,%7}, {%8,%9}, {%0,%1,%2,%3};"
                 : "+f"(d[0]), "+f"(d[1]), "+f"(d[2]), "+f"(d[3])
                 : "r"(a[0]), "r"(a[1]), "r"(a[2]), "r"(a[3]), "r"(b0), "r"(b1));
}

__device__ __forceinline__ uint32_t pack2(bf16 a, bf16 b) {
    __nv_bfloat162 t; t.x = a; t.y = b;
    return *reinterpret_cast<uint32_t*>(&t);
}
__device__ __forceinline__ void split1(float v, bf16& hi, bf16& lo) {
    hi = __float2bfloat16_rn(v);
    lo = __float2bfloat16_rn(v - __bfloat162float(hi));
}

// ---------------------------------------------------------------------------
// hgemm: C[M,N] = alpha * A[M,K] * B[N,K]^T  in bf16x3.
// CTA tile 128x128x64, 256 threads (8 warps, 4x2, warptile 32x64),
// 3-stage cp.async pipeline, xor swizzle.
// OUTMODE 0: fp32 C (alpha applied).  OUTMODE 1: bf16 hi/lo pair.
// ---------------------------------------------------------------------------
#define STAGE_BYTES 65536
#define T_AHI 0
#define T_ALO 16384
#define T_BHI 32768
#define T_BLO 49152
#define HG_SMEM (3 * STAGE_BYTES)

template <int OUTMODE>
__global__ __launch_bounds__(256, 1)
void hgemm(const bf16* __restrict__ Ahi, const bf16* __restrict__ Alo,
           const bf16* __restrict__ Bhi, const bf16* __restrict__ Blo,
           float* __restrict__ Cf, bf16* __restrict__ Chi, bf16* __restrict__ Clo,
           int K, int ldC, float alpha,
           size_t strA, size_t strB, size_t strC)
{
    extern __shared__ __align__(128) char smem[];
    const uint32_t sb = smem_u32(smem);

    const int tid  = threadIdx.x;
    const int lane = tid & 31;
    const int wid  = tid >> 5;
    const int wm   = wid & 3;          // 4 warp rows (m)
    const int wn   = wid >> 2;         // 2 warp cols (n)

    const size_t bz = blockIdx.z;
    Ahi += bz * strA;  Alo += bz * strA;
    Bhi += bz * strB;  Blo += bz * strB;
    const int row0 = blockIdx.y * 128;
    const int col0 = blockIdx.x * 128;

    // ---- cp.async loader: chunks c = tid + i*256, row = c>>3, col16 = c&7 --
    auto load_stage = [&](int s, int kiter) {
        const int k0 = kiter * 64;
        const uint32_t stb = sb + s * STAGE_BYTES;
#pragma unroll
        for (int i = 0; i < 4; i++) {
            const int c    = tid + i * 256;
            const int row  = c >> 3;
            const int c16  = c & 7;
            const uint32_t soff = (uint32_t)(row * 128 + ((c16 ^ (row & 7)) << 4));
            const size_t goffA = (size_t)(row0 + row) * K + k0 + c16 * 8;
            const size_t goffB = (size_t)(col0 + row) * K + k0 + c16 * 8;
            cp_async16(stb + T_AHI + soff, Ahi + goffA);
            cp_async16(stb + T_ALO + soff, Alo + goffA);
            cp_async16(stb + T_BHI + soff, Bhi + goffB);
            cp_async16(stb + T_BLO + soff, Blo + goffB);
        }
    };

    // ---- ldmatrix per-lane geometry ---------------------------------------
    const int lr16 = lane & 15;
    const int lhi  = lane >> 4;             // 0/1 -> k-halves of 16B cols
    int arow[2], brow[4];
#pragma unroll
    for (int mt = 0; mt < 2; mt++) arow[mt] = wm * 32 + mt * 16 + lr16;
#pragma unroll
    for (int np = 0; np < 4; np++) brow[np] = wn * 64 + np * 16 + lr16;

    auto smaddr = [&](int row, int cb) -> uint32_t {
        return (uint32_t)(row * 128 + (((cb ^ row) & 7) << 4));
    };

    float acc[2][8][4];
#pragma unroll
    for (int a = 0; a < 2; a++)
#pragma unroll
        for (int b = 0; b < 8; b++)
#pragma unroll
            for (int r = 0; r < 4; r++) acc[a][b][r] = 0.f;

    const int niter = K / 64;

    // ---- prologue ---------------------------------------------------------
    load_stage(0, 0); CP_COMMIT();
    load_stage(1, 1); CP_COMMIT();
    CP_WAIT1();
    __syncthreads();

    int s = 0, pf = 2;
    for (int it = 0; it < niter; ++it) {
        const uint32_t stb = sb + s * STAGE_BYTES;
        // ---- compute stage s ----
#pragma unroll
        for (int kk = 0; kk < 4; kk++) {
            const int cb = kk * 2 + lhi;
            uint32_t ah[2][4], al[2][4];
#pragma unroll
            for (int mt = 0; mt < 2; mt++) {
                const uint32_t off = smaddr(arow[mt], cb);
                ldm_x4(ah[mt], stb + T_AHI + off);
                ldm_x4(al[mt], stb + T_ALO + off);
            }
#pragma unroll
            for (int np = 0; np < 4; np++) {
                uint32_t bh[4], bl[4];
                const uint32_t off = smaddr(brow[np], cb);
                ldm_x4(bh, stb + T_BHI + off);
                ldm_x4(bl, stb + T_BLO + off);
#pragma unroll
                for (int mt = 0; mt < 2; mt++) {
#pragma unroll
                    for (int sub = 0; sub < 2; sub++) {
                        float* d = acc[mt][np * 2 + sub];
                        mma16816(d, ah[mt], bh[sub], bh[sub + 2]);
                        mma16816(d, al[mt], bh[sub], bh[sub + 2]);
                        mma16816(d, ah[mt], bl[sub], bl[sub + 2]);
                    }
                }
            }
        }
        // ---- prefetch / rotate ----
        if (it + 2 < niter) {
            load_stage(pf, it + 2);
            CP_COMMIT();
            CP_WAIT1();
        } else {
            CP_WAIT0();
        }
        __syncthreads();
        s  = (s  == 2) ? 0 : s  + 1;
        pf = (pf == 2) ? 0 : pf + 1;
    }

    // ---- epilogue ---------------------------------------------------------
    const int gi = lane >> 2;
    const int ti = lane & 3;
#pragma unroll
    for (int mt = 0; mt < 2; mt++) {
#pragma unroll
        for (int nt = 0; nt < 8; nt++) {
            const int col = col0 + wn * 64 + nt * 8 + ti * 2;
#pragma unroll
            for (int h = 0; h < 2; h++) {
                const size_t row = row0 + wm * 32 + mt * 16 + gi + h * 8;
                const float v0 = acc[mt][nt][h * 2 + 0] * alpha;
                const float v1 = acc[mt][nt][h * 2 + 1] * alpha;
                const size_t off = (strC * bz) + row * ldC + col;
                if (OUTMODE == 0) {
                    float2 f2; f2.x = v0; f2.y = v1;
                    *reinterpret_cast<float2*>(Cf + off) = f2;
                } else {
                    bf16 h0, l0, h1, l1;
                    split1(v0, h0, l0);
                    split1(v1, h1, l1);
                    *reinterpret_cast<uint32_t*>(Chi + off) = pack2(h0, h1);
                    *reinterpret_cast<uint32_t*>(Clo + off) = pack2(l0, l1);
                }
            }
        }
    }
}

// ---------------------------------------------------------------------------
// split: fp32 -> bf16 hi/lo (4 elems/thread)
// ---------------------------------------------------------------------------
__global__ __launch_bounds__(256)
void split_kernel(const float* __restrict__ src, bf16* __restrict__ hi,
                  bf16* __restrict__ lo, int n4)
{
    const int i = blockIdx.x * 256 + threadIdx.x;
    if (i >= n4) return;
    float4 v = reinterpret_cast<const float4*>(src)[i];
    bf16 hx, lx, hy, ly, hz, lz, hw, lw;
    split1(v.x, hx, lx); split1(v.y, hy, ly);
    split1(v.z, hz, lz); split1(v.w, hw, lw);
    uint2 ph; ph.x = pack2(hx, hy); ph.y = pack2(hz, hw);
    uint2 pl; pl.x = pack2(lx, ly); pl.y = pack2(lz, lw);
    reinterpret_cast<uint2*>(hi)[i] = ph;
    reinterpret_cast<uint2*>(lo)[i] = pl;
}

// ---------------------------------------------------------------------------
// bf16 transpose per batch: dst[v][s] = src[s][v]
// ---------------------------------------------------------------------------
__global__ __launch_bounds__(256)
void transpose_bf16(const bf16* __restrict__ src, bf16* __restrict__ dst)
{
    __shared__ bf16 t[32][33];
    const bf16* s = src + (size_t)blockIdx.z * SEQ * DMODEL;
    bf16*       o = dst + (size_t)blockIdx.z * SEQ * DMODEL;
    const int s0 = blockIdx.x * 32;
    const int v0 = blockIdx.y * 32;
    const int tx = threadIdx.x & 31, ty = threadIdx.x >> 5;
#pragma unroll
    for (int r = 0; r < 4; r++)
        t[ty + r * 8][tx] = s[(size_t)(s0 + ty + r * 8) * DMODEL + v0 + tx];
    __syncthreads();
#pragma unroll
    for (int r = 0; r < 4; r++)
        o[(size_t)(v0 + ty + r * 8) * SEQ + s0 + tx] = t[tx][ty + r * 8];
}

// ---------------------------------------------------------------------------
// softmax row (2048) fp32 -> P bf16 hi/lo
// ---------------------------------------------------------------------------
__global__ __launch_bounds__(256)
void softmax_kernel(const float* __restrict__ S, bf16* __restrict__ Phi,
                    bf16* __restrict__ Plo)
{
    const size_t r0 = (size_t)blockIdx.x * SEQ;
    const float* row = S + r0;
    const int tid = threadIdx.x;

    float4 v0 = reinterpret_cast<const float4*>(row)[tid];
    float4 v1 = reinterpret_cast<const float4*>(row)[tid + 256];

    float m = fmaxf(fmaxf(fmaxf(v0.x, v0.y), fmaxf(v0.z, v0.w)),
                    fmaxf(fmaxf(v1.x, v1.y), fmaxf(v1.z, v1.w)));
    __shared__ float red[8];
#pragma unroll
    for (int o = 16; o > 0; o >>= 1)
        m = fmaxf(m, __shfl_xor_sync(0xffffffffu, m, o));
    if ((tid & 31) == 0) red[tid >> 5] = m;
    __syncthreads();
    m = red[0];
#pragma unroll
    for (int w = 1; w < 8; w++) m = fmaxf(m, red[w]);
    __syncthreads();

    v0.x = __expf(v0.x - m); v0.y = __expf(v0.y - m);
    v0.z = __expf(v0.z - m); v0.w = __expf(v0.w - m);
    v1.x = __expf(v1.x - m); v1.y = __expf(v1.y - m);
    v1.z = __expf(v1.z - m); v1.w = __expf(v1.w - m);

    float sum = (v0.x + v0.y + v0.z + v0.w) + (v1.x + v1.y + v1.z + v1.w);
#pragma unroll
    for (int o = 16; o > 0; o >>= 1)
        sum += __shfl_xor_sync(0xffffffffu, sum, o);
    if ((tid & 31) == 0) red[tid >> 5] = sum;
    __syncthreads();
    sum = red[0];
#pragma unroll
    for (int w = 1; w < 8; w++) sum += red[w];
    const float inv = 1.0f / sum;

    auto emit = [&](float4 v, int idx) {
        bf16 h0, l0, h1, l1, h2, l2, h3, l3;
        split1(v.x * inv, h0, l0); split1(v.y * inv, h1, l1);
        split1(v.z * inv, h2, l2); split1(v.w * inv, h3, l3);
        uint2 ph; ph.x = pack2(h0, h1); ph.y = pack2(h2, h3);
        uint2 pl; pl.x = pack2(l0, l1); pl.y = pack2(l2, l3);
        reinterpret_cast<uint2*>(Phi + r0)[idx] = ph;
        reinterpret_cast<uint2*>(Plo + r0)[idx] = pl;
    };
    emit(v0, tid);
    emit(v1, tid + 256);
}

// ---------------------------------------------------------------------------
// Launch
// ---------------------------------------------------------------------------
extern "C" void kernel_launch(void* const* d_in, const int* in_sizes, int n_in,
                              void* d_out, int out_size)
{
    const float* x  = (const float*)d_in[0];
    const float* w[4] = {(const float*)d_in[1], (const float*)d_in[2],
                         (const float*)d_in[3], (const float*)d_in[4]};
    float* out = (float*)d_out;

    bf16 *xhi, *xlo, *whi, *wlo, *Qhi, *Qlo, *Khi, *Klo, *Vhi, *Vlo,
         *Vthi, *Vtlo, *Phi, *Plo, *Chi, *Clo;
    float* S;
    cudaGetSymbolAddress((void**)&xhi,  g_xhi);
    cudaGetSymbolAddress((void**)&xlo,  g_xlo);
    cudaGetSymbolAddress((void**)&whi,  g_whi);
    cudaGetSymbolAddress((void**)&wlo,  g_wlo);
    cudaGetSymbolAddress((void**)&Qhi,  g_Qhi);
    cudaGetSymbolAddress((void**)&Qlo,  g_Qlo);
    cudaGetSymbolAddress((void**)&Khi,  g_Khi);
    cudaGetSymbolAddress((void**)&Klo,  g_Klo);
    cudaGetSymbolAddress((void**)&Vhi,  g_Vhi);
    cudaGetSymbolAddress((void**)&Vlo,  g_Vlo);
    cudaGetSymbolAddress((void**)&Vthi, g_Vthi);
    cudaGetSymbolAddress((void**)&Vtlo, g_Vtlo);
    cudaGetSymbolAddress((void**)&S,    g_S);
    cudaGetSymbolAddress((void**)&Phi,  g_Phi);
    cudaGetSymbolAddress((void**)&Plo,  g_Plo);
    cudaGetSymbolAddress((void**)&Chi,  g_Chi);
    cudaGetSymbolAddress((void**)&Clo,  g_Clo);

    cudaFuncSetAttribute(hgemm<0>, cudaFuncAttributeMaxDynamicSharedMemorySize, HG_SMEM);
    cudaFuncSetAttribute(hgemm<1>, cudaFuncAttributeMaxDynamicSharedMemorySize, HG_SMEM);

    const dim3 blk(256);
    const size_t WSTR = (size_t)DMODEL * DMODEL;

    // splits
    split_kernel<<<MTOT * DMODEL / 1024, blk>>>(x, xhi, xlo, MTOT * DMODEL / 4);
    for (int i = 0; i < 4; i++)
        split_kernel<<<DMODEL * DMODEL / 1024, blk>>>(w[i], whi + i * WSTR,
                                                      wlo + i * WSTR,
                                                      DMODEL * DMODEL / 4);

    // projections -> bf16 hi/lo
    {
        dim3 grid(DMODEL / 128, MTOT / 128, 1);
        hgemm<1><<<grid, blk, HG_SMEM>>>(xhi, xlo, whi + 0 * WSTR, wlo + 0 * WSTR,
                                         nullptr, Qhi, Qlo, DMODEL, DMODEL, 1.f, 0, 0, 0);
        hgemm<1><<<grid, blk, HG_SMEM>>>(xhi, xlo, whi + 1 * WSTR, wlo + 1 * WSTR,
                                         nullptr, Khi, Klo, DMODEL, DMODEL, 1.f, 0, 0, 0);
        hgemm<1><<<grid, blk, HG_SMEM>>>(xhi, xlo, whi + 2 * WSTR, wlo + 2 * WSTR,
                                         nullptr, Vhi, Vlo, DMODEL, DMODEL, 1.f, 0, 0, 0);
    }

    // V transpose (hi, lo)
    {
        dim3 g(SEQ / 32, DMODEL / 32, BATCH);
        transpose_bf16<<<g, blk>>>(Vhi, Vthi);
        transpose_bf16<<<g, blk>>>(Vlo, Vtlo);
    }

    // S = Q K^T / 32 (fp32)
    {
        dim3 grid(SEQ / 128, SEQ / 128, BATCH);
        hgemm<0><<<grid, blk, HG_SMEM>>>(Qhi, Qlo, Khi, Klo, S, nullptr, nullptr,
                                         DMODEL, SEQ, 0.03125f,
                                         (size_t)SEQ * DMODEL,
                                         (size_t)SEQ * DMODEL,
                                         (size_t)SEQ * SEQ);
    }

    // softmax -> P hi/lo
    softmax_kernel<<<MTOT, blk>>>(S, Phi, Plo);

    // ctx = P Vt^T -> bf16 hi/lo  (K = SEQ)
    {
        dim3 grid(DMODEL / 128, SEQ / 128, BATCH);
        hgemm<1><<<grid, blk, HG_SMEM>>>(Phi, Plo, Vthi, Vtlo, nullptr, Chi, Clo,
                                         SEQ, DMODEL, 1.f,
                                         (size_t)SEQ * SEQ,
                                         (size_t)DMODEL * SEQ,
                                         (size_t)SEQ * DMODEL);
    }

    // out = ctx wo^T (fp32)
    {
        dim3 grid(DMODEL / 128, MTOT / 128, 1);
        hgemm<0><<<grid, blk, HG_SMEM>>>(Chi, Clo, whi + 3 * WSTR, wlo + 3 * WSTR,
                                         out, nullptr, nullptr,
                                         DMODEL, DMODEL, 1.f, 0, 0, 0);
    }
}

// round 8
// speedup vs baseline: 2.6650x; 1.0115x over previous
#include <cuda_runtime.h>
#include <cuda_bf16.h>
#include <cstdint>

// ===========================================================================
// Encoder (single-head attention, d=1024, batch 8, seq 2048).
// Target compiles as plain sm_100 (no 'a') -> no tcgen05/TMEM; tensor path is
// ldmatrix + mma.sync.m16n8k16 bf16 (HMMA) with bf16x3 hi/lo split:
//   A*B ~= Ahi*Bhi + Alo*Bhi + Ahi*Blo   (error ~2^-18, fp32 accum)
// All GEMMs NT.
// R6b/R7: K-chunk 64 -> 32 (stage 32KB, 3 stages = 96KB smem) + launch_bounds
// (256,2) => 2 CTAs/SM (16 warps) to hide stage-boundary + ldmatrix latency.
// ===========================================================================

#define BATCH   8
#define SEQ     2048
#define DMODEL  1024
#define MTOT    (BATCH * SEQ)

typedef __nv_bfloat16 bf16;

// ---- static device scratch ------------------------------------------------
__device__ bf16 g_xhi [MTOT * DMODEL];
__device__ bf16 g_xlo [MTOT * DMODEL];
__device__ bf16 g_whi [4][DMODEL * DMODEL];   // q,k,v,o
__device__ bf16 g_wlo [4][DMODEL * DMODEL];
__device__ bf16 g_Qhi [MTOT * DMODEL];
__device__ bf16 g_Qlo [MTOT * DMODEL];
__device__ bf16 g_Khi [MTOT * DMODEL];
__device__ bf16 g_Klo [MTOT * DMODEL];
__device__ bf16 g_Vhi [MTOT * DMODEL];
__device__ bf16 g_Vlo [MTOT * DMODEL];
__device__ bf16 g_Vthi[MTOT * DMODEL];
__device__ bf16 g_Vtlo[MTOT * DMODEL];
__device__ float g_S  [(size_t)BATCH * SEQ * SEQ];
__device__ bf16 g_Phi [(size_t)BATCH * SEQ * SEQ];
__device__ bf16 g_Plo [(size_t)BATCH * SEQ * SEQ];
__device__ bf16 g_Chi [MTOT * DMODEL];
__device__ bf16 g_Clo [MTOT * DMODEL];

// ---- PTX helpers ----------------------------------------------------------
__device__ __forceinline__ uint32_t smem_u32(const void* p) {
    uint32_t a;
    asm("{ .reg .u64 t; cvta.to.shared.u64 t, %1; cvt.u32.u64 %0, t; }"
        : "=r"(a) : "l"(p));
    return a;
}

__device__ __forceinline__ void cp_async16(uint32_t dst, const void* src) {
    asm volatile("cp.async.cg.shared.global [%0], [%1], 16;"
                 :: "r"(dst), "l"(src) : "memory");
}
#define CP_COMMIT() asm volatile("cp.async.commit_group;" ::: "memory")
#define CP_WAIT1()  asm volatile("cp.async.wait_group 1;"  ::: "memory")
#define CP_WAIT0()  asm volatile("cp.async.wait_group 0;"  ::: "memory")

__device__ __forceinline__ void ldm_x4(uint32_t* r, uint32_t addr) {
    asm volatile("ldmatrix.sync.aligned.m8n8.x4.shared.b16 {%0,%1,%2,%3}, [%4];"
                 : "=r"(r[0]), "=r"(r[1]), "=r"(r[2]), "=r"(r[3]) : "r"(addr));
}

__device__ __forceinline__ void mma16816(float* d, const uint32_t* a,
                                         uint32_t b0, uint32_t b1) {
    asm volatile("mma.sync.aligned.m16n8k16.row.col.f32.bf16.bf16.f32 "
                 "{%0,%1,%2,%3}, {%4,%5,%6,%7}, {%8,%9}, {%0,%1,%2,%3};"
                 : "+f"(d[0]), "+f"(d[1]), "+f"(d[2]), "+f"(d[3])
                 : "r"(a[0]), "r"(a[1]), "r"(a[2]), "r"(a[3]), "r"(b0), "r"(b1));
}

__device__ __forceinline__ uint32_t pack2(bf16 a, bf16 b) {
    __nv_bfloat162 t; t.x = a; t.y = b;
    return *reinterpret_cast<uint32_t*>(&t);
}
__device__ __forceinline__ void split1(float v, bf16& hi, bf16& lo) {
    hi = __float2bfloat16_rn(v);
    lo = __float2bfloat16_rn(v - __bfloat162float(hi));
}

// ---------------------------------------------------------------------------
// hgemm: C[M,N] = alpha * A[M,K] * B[N,K]^T  in bf16x3.
// CTA tile 128x128x32, 256 threads (8 warps, 4x2, warptile 32x64),
// 3-stage cp.async pipeline (32KB/stage, 96KB total -> 2 CTAs/SM).
// Rows are 64B (32 bf16); swizzle: col16' = col16 ^ ((row>>1)&3): the 8 rows
// of any ldmatrix hit 8 distinct 16B banks (row&1 gives the 64B phase, the
// xor permutes the 4 columns across row pairs). Conflict-free.
// OUTMODE 0: fp32 C (alpha applied).  OUTMODE 1: bf16 hi/lo pair.
// ---------------------------------------------------------------------------
#define GBK 32
#define STAGE_BYTES 32768
#define T_AHI 0
#define T_ALO 8192
#define T_BHI 16384
#define T_BLO 24576
#define HG_SMEM (3 * STAGE_BYTES)

template <int OUTMODE>
__global__ __launch_bounds__(256, 2)
void hgemm(const bf16* __restrict__ Ahi, const bf16* __restrict__ Alo,
           const bf16* __restrict__ Bhi, const bf16* __restrict__ Blo,
           float* __restrict__ Cf, bf16* __restrict__ Chi, bf16* __restrict__ Clo,
           int K, int ldC, float alpha,
           size_t strA, size_t strB, size_t strC)
{
    extern __shared__ __align__(128) char smem[];
    const uint32_t sb = smem_u32(smem);

    const int tid  = threadIdx.x;
    const int lane = tid & 31;
    const int wid  = tid >> 5;
    const int wm   = wid & 3;
    const int wn   = wid >> 2;

    const size_t bz = blockIdx.z;
    Ahi += bz * strA;  Alo += bz * strA;
    Bhi += bz * strB;  Blo += bz * strB;
    const int row0 = blockIdx.y * 128;
    const int col0 = blockIdx.x * 128;

    // 512 16B-chunks per tile type; 2 per thread per type.
    auto load_stage = [&](int s, int kiter) {
        const int k0 = kiter * GBK;
        const uint32_t stb = sb + s * STAGE_BYTES;
#pragma unroll
        for (int i = 0; i < 2; i++) {
            const int c    = tid + i * 256;
            const int row  = c >> 2;              // 0..127
            const int c16  = c & 3;               // 0..3 (16B col)
            const uint32_t soff =
                (uint32_t)(row * 64 + (((c16 ^ ((row >> 1) & 3)) & 3) << 4));
            const size_t goffA = (size_t)(row0 + row) * K + k0 + c16 * 8;
            const size_t goffB = (size_t)(col0 + row) * K + k0 + c16 * 8;
            cp_async16(stb + T_AHI + soff, Ahi + goffA);
            cp_async16(stb + T_ALO + soff, Alo + goffA);
            cp_async16(stb + T_BHI + soff, Bhi + goffB);
            cp_async16(stb + T_BLO + soff, Blo + goffB);
        }
    };

    const int lr16 = lane & 15;
    const int lhi  = lane >> 4;
    int arow[2], brow[4];
#pragma unroll
    for (int mt = 0; mt < 2; mt++) arow[mt] = wm * 32 + mt * 16 + lr16;
#pragma unroll
    for (int np = 0; np < 4; np++) brow[np] = wn * 64 + np * 16 + lr16;

    auto smaddr = [&](int row, int cb) -> uint32_t {
        return (uint32_t)(row * 64 + (((cb ^ ((row >> 1) & 3)) & 3) << 4));
    };

    float acc[2][8][4];
#pragma unroll
    for (int a = 0; a < 2; a++)
#pragma unroll
        for (int b = 0; b < 8; b++)
#pragma unroll
            for (int r = 0; r < 4; r++) acc[a][b][r] = 0.f;

    const int niter = K / GBK;

    load_stage(0, 0); CP_COMMIT();
    load_stage(1, 1); CP_COMMIT();
    CP_WAIT1();
    __syncthreads();

    int s = 0, pf = 2;
    for (int it = 0; it < niter; ++it) {
        const uint32_t stb = sb + s * STAGE_BYTES;
#pragma unroll
        for (int kk = 0; kk < 2; kk++) {
            const int cb = kk * 2 + lhi;          // 0..3
            uint32_t ah[2][4], al[2][4];
#pragma unroll
            for (int mt = 0; mt < 2; mt++) {
                const uint32_t off = smaddr(arow[mt], cb);
                ldm_x4(ah[mt], stb + T_AHI + off);
                ldm_x4(al[mt], stb + T_ALO + off);
            }
#pragma unroll
            for (int np = 0; np < 4; np++) {
                uint32_t bh[4], bl[4];
                const uint32_t off = smaddr(brow[np], cb);
                ldm_x4(bh, stb + T_BHI + off);
                ldm_x4(bl, stb + T_BLO + off);
#pragma unroll
                for (int mt = 0; mt < 2; mt++) {
#pragma unroll
                    for (int sub = 0; sub < 2; sub++) {
                        float* d = acc[mt][np * 2 + sub];
                        mma16816(d, ah[mt], bh[sub], bh[sub + 2]);
                        mma16816(d, al[mt], bh[sub], bh[sub + 2]);
                        mma16816(d, ah[mt], bl[sub], bl[sub + 2]);
                    }
                }
            }
        }
        if (it + 2 < niter) {
            load_stage(pf, it + 2);
            CP_COMMIT();
            CP_WAIT1();
        } else {
            CP_WAIT0();
        }
        __syncthreads();
        s  = (s  == 2) ? 0 : s  + 1;
        pf = (pf == 2) ? 0 : pf + 1;
    }

    const int gi = lane >> 2;
    const int ti = lane & 3;
#pragma unroll
    for (int mt = 0; mt < 2; mt++) {
#pragma unroll
        for (int nt = 0; nt < 8; nt++) {
            const int col = col0 + wn * 64 + nt * 8 + ti * 2;
#pragma unroll
            for (int h = 0; h < 2; h++) {
                const size_t row = row0 + wm * 32 + mt * 16 + gi + h * 8;
                const float v0 = acc[mt][nt][h * 2 + 0] * alpha;
                const float v1 = acc[mt][nt][h * 2 + 1] * alpha;
                const size_t off = (strC * bz) + row * ldC + col;
                if (OUTMODE == 0) {
                    float2 f2; f2.x = v0; f2.y = v1;
                    *reinterpret_cast<float2*>(Cf + off) = f2;
                } else {
                    bf16 h0, l0, h1, l1;
                    split1(v0, h0, l0);
                    split1(v1, h1, l1);
                    *reinterpret_cast<uint32_t*>(Chi + off) = pack2(h0, h1);
                    *reinterpret_cast<uint32_t*>(Clo + off) = pack2(l0, l1);
                }
            }
        }
    }
}

// ---------------------------------------------------------------------------
// split: fp32 -> bf16 hi/lo (x input; one launch)
// ---------------------------------------------------------------------------
__global__ __launch_bounds__(256)
void split_kernel(const float* __restrict__ src, bf16* __restrict__ hi,
                  bf16* __restrict__ lo, int n4)
{
    const int i = blockIdx.x * 256 + threadIdx.x;
    if (i >= n4) return;
    float4 v = reinterpret_cast<const float4*>(src)[i];
    bf16 hx, lx, hy, ly, hz, lz, hw, lw;
    split1(v.x, hx, lx); split1(v.y, hy, ly);
    split1(v.z, hz, lz); split1(v.w, hw, lw);
    uint2 ph; ph.x = pack2(hx, hy); ph.y = pack2(hz, hw);
    uint2 pl; pl.x = pack2(lx, ly); pl.y = pack2(lz, lw);
    reinterpret_cast<uint2*>(hi)[i] = ph;
    reinterpret_cast<uint2*>(lo)[i] = pl;
}

// all 4 weights in one launch: grid.z selects the weight
struct WPtrs { const float* src[4]; bf16* hi; bf16* lo; };
__global__ __launch_bounds__(256)
void split_w_kernel(WPtrs p, int n4)
{
    const int z = blockIdx.z;
    const int i = blockIdx.x * 256 + threadIdx.x;
    if (i >= n4) return;
    const size_t wstr = (size_t)DMODEL * DMODEL / 4;   // in uint2 units
    float4 v = reinterpret_cast<const float4*>(p.src[z])[i];
    bf16 hx, lx, hy, ly, hz, lz, hw, lw;
    split1(v.x, hx, lx); split1(v.y, hy, ly);
    split1(v.z, hz, lz); split1(v.w, hw, lw);
    uint2 ph; ph.x = pack2(hx, hy); ph.y = pack2(hz, hw);
    uint2 pl; pl.x = pack2(lx, ly); pl.y = pack2(lz, lw);
    reinterpret_cast<uint2*>(p.hi)[z * wstr + i] = ph;
    reinterpret_cast<uint2*>(p.lo)[z * wstr + i] = pl;
}

// ---------------------------------------------------------------------------
// bf16 transpose per batch, hi+lo in one launch: z = batch*2 + sel
// ---------------------------------------------------------------------------
__global__ __launch_bounds__(256)
void transpose_bf16(const bf16* __restrict__ srch, const bf16* __restrict__ srcl,
                    bf16* __restrict__ dsth, bf16* __restrict__ dstl)
{
    __shared__ bf16 t[32][33];
    const int b   = blockIdx.z >> 1;
    const int sel = blockIdx.z & 1;
    const bf16* s = (sel ? srcl : srch) + (size_t)b * SEQ * DMODEL;
    bf16*       o = (sel ? dstl : dsth) + (size_t)b * SEQ * DMODEL;
    const int s0 = blockIdx.x * 32;
    const int v0 = blockIdx.y * 32;
    const int tx = threadIdx.x & 31, ty = threadIdx.x >> 5;
#pragma unroll
    for (int r = 0; r < 4; r++)
        t[ty + r * 8][tx] = s[(size_t)(s0 + ty + r * 8) * DMODEL + v0 + tx];
    __syncthreads();
#pragma unroll
    for (int r = 0; r < 4; r++)
        o[(size_t)(v0 + ty + r * 8) * SEQ + s0 + tx] = t[tx][ty + r * 8];
}

// ---------------------------------------------------------------------------
// softmax row (2048) fp32 -> P bf16 hi/lo
// ---------------------------------------------------------------------------
__global__ __launch_bounds__(256)
void softmax_kernel(const float* __restrict__ S, bf16* __restrict__ Phi,
                    bf16* __restrict__ Plo)
{
    const size_t r0 = (size_t)blockIdx.x * SEQ;
    const float* row = S + r0;
    const int tid = threadIdx.x;

    float4 v0 = reinterpret_cast<const float4*>(row)[tid];
    float4 v1 = reinterpret_cast<const float4*>(row)[tid + 256];

    float m = fmaxf(fmaxf(fmaxf(v0.x, v0.y), fmaxf(v0.z, v0.w)),
                    fmaxf(fmaxf(v1.x, v1.y), fmaxf(v1.z, v1.w)));
    __shared__ float red[8];
#pragma unroll
    for (int o = 16; o > 0; o >>= 1)
        m = fmaxf(m, __shfl_xor_sync(0xffffffffu, m, o));
    if ((tid & 31) == 0) red[tid >> 5] = m;
    __syncthreads();
    m = red[0];
#pragma unroll
    for (int w = 1; w < 8; w++) m = fmaxf(m, red[w]);
    __syncthreads();

    v0.x = __expf(v0.x - m); v0.y = __expf(v0.y - m);
    v0.z = __expf(v0.z - m); v0.w = __expf(v0.w - m);
    v1.x = __expf(v1.x - m); v1.y = __expf(v1.y - m);
    v1.z = __expf(v1.z - m); v1.w = __expf(v1.w - m);

    float sum = (v0.x + v0.y + v0.z + v0.w) + (v1.x + v1.y + v1.z + v1.w);
#pragma unroll
    for (int o = 16; o > 0; o >>= 1)
        sum += __shfl_xor_sync(0xffffffffu, sum, o);
    if ((tid & 31) == 0) red[tid >> 5] = sum;
    __syncthreads();
    sum = red[0];
#pragma unroll
    for (int w = 1; w < 8; w++) sum += red[w];
    const float inv = 1.0f / sum;

    auto emit = [&](float4 v, int idx) {
        bf16 h0, l0, h1, l1, h2, l2, h3, l3;
        split1(v.x * inv, h0, l0); split1(v.y * inv, h1, l1);
        split1(v.z * inv, h2, l2); split1(v.w * inv, h3, l3);
        uint2 ph; ph.x = pack2(h0, h1); ph.y = pack2(h2, h3);
        uint2 pl; pl.x = pack2(l0, l1); pl.y = pack2(l2, l3);
        reinterpret_cast<uint2*>(Phi + r0)[idx] = ph;
        reinterpret_cast<uint2*>(Plo + r0)[idx] = pl;
    };
    emit(v0, tid);
    emit(v1, tid + 256);
}

// ---------------------------------------------------------------------------
// Launch
// ---------------------------------------------------------------------------
extern "C" void kernel_launch(void* const* d_in, const int* in_sizes, int n_in,
                              void* d_out, int out_size)
{
    const float* x  = (const float*)d_in[0];
    float* out = (float*)d_out;

    bf16 *xhi, *xlo, *whi, *wlo, *Qhi, *Qlo, *Khi, *Klo, *Vhi, *Vlo,
         *Vthi, *Vtlo, *Phi, *Plo, *Chi, *Clo;
    float* S;
    cudaGetSymbolAddress((void**)&xhi,  g_xhi);
    cudaGetSymbolAddress((void**)&xlo,  g_xlo);
    cudaGetSymbolAddress((void**)&whi,  g_whi);
    cudaGetSymbolAddress((void**)&wlo,  g_wlo);
    cudaGetSymbolAddress((void**)&Qhi,  g_Qhi);
    cudaGetSymbolAddress((void**)&Qlo,  g_Qlo);
    cudaGetSymbolAddress((void**)&Khi,  g_Khi);
    cudaGetSymbolAddress((void**)&Klo,  g_Klo);
    cudaGetSymbolAddress((void**)&Vhi,  g_Vhi);
    cudaGetSymbolAddress((void**)&Vlo,  g_Vlo);
    cudaGetSymbolAddress((void**)&Vthi, g_Vthi);
    cudaGetSymbolAddress((void**)&Vtlo, g_Vtlo);
    cudaGetSymbolAddress((void**)&S,    g_S);
    cudaGetSymbolAddress((void**)&Phi,  g_Phi);
    cudaGetSymbolAddress((void**)&Plo,  g_Plo);
    cudaGetSymbolAddress((void**)&Chi,  g_Chi);
    cudaGetSymbolAddress((void**)&Clo,  g_Clo);

    cudaFuncSetAttribute(hgemm<0>, cudaFuncAttributeMaxDynamicSharedMemorySize, HG_SMEM);
    cudaFuncSetAttribute(hgemm<1>, cudaFuncAttributeMaxDynamicSharedMemorySize, HG_SMEM);

    const dim3 blk(256);
    const size_t WSTR = (size_t)DMODEL * DMODEL;

    // #0: split x
    split_kernel<<<MTOT * DMODEL / 1024, blk>>>(x, xhi, xlo, MTOT * DMODEL / 4);

    // #1: split all 4 weights (merged launch)
    {
        WPtrs p;
        p.src[0] = (const float*)d_in[1];
        p.src[1] = (const float*)d_in[2];
        p.src[2] = (const float*)d_in[3];
        p.src[3] = (const float*)d_in[4];
        p.hi = whi; p.lo = wlo;
        dim3 g(DMODEL * DMODEL / 1024, 1, 4);
        split_w_kernel<<<g, blk>>>(p, DMODEL * DMODEL / 4);
    }

    // #2-#4: projections -> bf16 hi/lo
    {
        dim3 grid(DMODEL / 128, MTOT / 128, 1);
        hgemm<1><<<grid, blk, HG_SMEM>>>(xhi, xlo, whi + 0 * WSTR, wlo + 0 * WSTR,
                                         nullptr, Qhi, Qlo, DMODEL, DMODEL, 1.f, 0, 0, 0);
        hgemm<1><<<grid, blk, HG_SMEM>>>(xhi, xlo, whi + 1 * WSTR, wlo + 1 * WSTR,
                                         nullptr, Khi, Klo, DMODEL, DMODEL, 1.f, 0, 0, 0);
        hgemm<1><<<grid, blk, HG_SMEM>>>(xhi, xlo, whi + 2 * WSTR, wlo + 2 * WSTR,
                                         nullptr, Vhi, Vlo, DMODEL, DMODEL, 1.f, 0, 0, 0);
    }

    // #5: S = Q K^T / 32 (fp32)   <-- ncu -s 5 target
    {
        dim3 grid(SEQ / 128, SEQ / 128, BATCH);
        hgemm<0><<<grid, blk, HG_SMEM>>>(Qhi, Qlo, Khi, Klo, S, nullptr, nullptr,
                                         DMODEL, SEQ, 0.03125f,
                                         (size_t)SEQ * DMODEL,
                                         (size_t)SEQ * DMODEL,
                                         (size_t)SEQ * SEQ);
    }

    // #6: V transpose (hi + lo merged)
    {
        dim3 g(SEQ / 32, DMODEL / 32, BATCH * 2);
        transpose_bf16<<<g, blk>>>(Vhi, Vlo, Vthi, Vtlo);
    }

    // #7: softmax -> P hi/lo
    softmax_kernel<<<MTOT, blk>>>(S, Phi, Plo);

    // #8: ctx = P Vt^T -> bf16 hi/lo  (K = SEQ)
    {
        dim3 grid(DMODEL / 128, SEQ / 128, BATCH);
        hgemm<1><<<grid, blk, HG_SMEM>>>(Phi, Plo, Vthi, Vtlo, nullptr, Chi, Clo,
                                         SEQ, DMODEL, 1.f,
                                         (size_t)SEQ * SEQ,
                                         (size_t)DMODEL * SEQ,
                                         (size_t)SEQ * DMODEL);
    }

    // #9: out = ctx wo^T (fp32)
    {
        dim3 grid(DMODEL / 128, MTOT / 128, 1);
        hgemm<0><<<grid, blk, HG_SMEM>>>(Chi, Clo, whi + 3 * WSTR, wlo + 3 * WSTR,
                                         out, nullptr, nullptr,
                                         DMODEL, DMODEL, 1.f, 0, 0, 0);
    }
}